// round 14
// baseline (speedup 1.0000x reference)
#include <cuda_runtime.h>
#include <cuda_fp16.h>
#include <cstdint>

// ============================================================================
// MultiHeadNet, R14: wave-structure round.
//  - GEMM2+GEMM3 fused in ONE launch; GEMM3 CTAs spin on per-mtile flags
//    released by GEMM2 CTAs (producer ids first in dispatch order).
//  - k_convert split in half; second half overlapped with GEMM1 first half.
// GEMM core: R11/13 (128x256 tile, 64x64 warp tiles, KC=128, HMMA fp16,
// ~512 MAC/cyc/SM pipe cap). rel_err ~5e-4 unchanged.
// ============================================================================

constexpr int BATCH  = 8192;
constexpr int NBITS  = 3;
constexpr int DFEAT  = 512;
constexpr int DBASE  = 1024;
constexpr int DH     = 1024;
constexpr int DOUT   = 512;
constexpr int NHEADS = 8;
constexpr int XSTRIDE = NBITS + DFEAT; // 515
constexpr int MAXTILES = 76;           // >= worst-case sum ceil(cnt_h/128)

constexpr int KC = 128;
constexpr int BN = 256;
constexpr int PITCH = 272;                          // 256 data + 16 pad
constexpr int A_PB = 128 * PITCH;                   // 34816
constexpr int B_PB = BN * PITCH;                    // 69632
constexpr int OFF_A = 0, OFF_B = A_PB;
constexpr int STAGE_B = A_PB + B_PB;                // 104448
constexpr int DSMEM_BYTES = 2 * STAGE_B + 1024;     // 209920

constexpr int G2_CTAS = (DH / BN) * MAXTILES;       // 304
constexpr int G3_CTAS = (DOUT / BN) * MAXTILES;     // 152

// ---------------- scratch (__device__ globals) -------------------------------
__device__ int g_counts[NHEADS];
__device__ int g_off[NHEADS];
__device__ int g_cursor[NHEADS];
__device__ int g_permsrc[BATCH];
__device__ int g_tilemap[MAXTILES];    // (head<<16) | mtile
__device__ int g_ntiles;
__device__ int g_tiledone[MAXTILES];   // GEMM2 completion counters (target 4)

__device__ __half g_x[(size_t)BATCH * DFEAT];
__device__ __half g_b[(size_t)BATCH * DBASE];
__device__ __half g_h[(size_t)BATCH * DH];
__device__ __half g_wbt[(size_t)DBASE * DFEAT];
__device__ __half g_w1t[(size_t)NHEADS * DH * DBASE];
__device__ __half g_w2t[(size_t)NHEADS * DOUT * DH];

// ---------------- streams + events -------------------------------------------
static cudaStream_t s_side = nullptr, s_rt = nullptr, s_cv = nullptr;
static cudaEvent_t s_fork = nullptr, s_ewb = nullptr, s_ew1 = nullptr,
                   s_ew2 = nullptr, s_ert = nullptr, s_ecvb = nullptr;
static struct SideInit {
    SideInit() {
        cudaStreamCreateWithFlags(&s_side, cudaStreamNonBlocking);
        cudaStreamCreateWithFlags(&s_rt,   cudaStreamNonBlocking);
        cudaStreamCreateWithFlags(&s_cv,   cudaStreamNonBlocking);
        cudaEventCreateWithFlags(&s_fork, cudaEventDisableTiming);
        cudaEventCreateWithFlags(&s_ewb,  cudaEventDisableTiming);
        cudaEventCreateWithFlags(&s_ew1,  cudaEventDisableTiming);
        cudaEventCreateWithFlags(&s_ew2,  cudaEventDisableTiming);
        cudaEventCreateWithFlags(&s_ert,  cudaEventDisableTiming);
        cudaEventCreateWithFlags(&s_ecvb, cudaEventDisableTiming);
    }
} s_side_init;

// ---------------- PTX helpers -------------------------------------------------
__device__ __forceinline__ uint32_t smem_u32(const void* p) {
    uint32_t a;
    asm("{ .reg .u64 t; cvta.to.shared.u64 t, %1; cvt.u32.u64 %0, t; }" : "=r"(a) : "l"(p));
    return a;
}
#define CP_ASYNC16(saddr, gptr) \
    asm volatile("cp.async.cg.shared.global [%0], [%1], 16;" :: "r"(saddr), "l"(gptr))
#define CP_COMMIT() asm volatile("cp.async.commit_group;" ::: "memory")
#define CP_WAIT1()  asm volatile("cp.async.wait_group 1;" ::: "memory")
#define CP_WAIT0()  asm volatile("cp.async.wait_group 0;" ::: "memory")

__device__ __forceinline__ uint32_t lds32(uint32_t saddr) {
    uint32_t v;
    asm volatile("ld.shared.b32 %0, [%1];" : "=r"(v) : "r"(saddr));
    return v;
}
__device__ __forceinline__ void mma16816(float* c, const uint32_t* a, const uint32_t* b) {
    asm volatile("mma.sync.aligned.m16n8k16.row.col.f32.f16.f16.f32 "
        "{%0,%1,%2,%3}, {%4,%5,%6,%7}, {%8,%9}, {%0,%1,%2,%3};"
        : "+f"(c[0]), "+f"(c[1]), "+f"(c[2]), "+f"(c[3])
        : "r"(a[0]), "r"(a[1]), "r"(a[2]), "r"(a[3]), "r"(b[0]), "r"(b[1]));
}

// ---------------- prep kernels -------------------------------------------------
__device__ __forceinline__ int head_of(const float* xr) {
    return (xr[0] > 0.5f ? 1 : 0) | (xr[1] > 0.5f ? 2 : 0) | (xr[2] > 0.5f ? 4 : 0);
}
__global__ void k_zeroc() {
    if (threadIdx.x < NHEADS) g_counts[threadIdx.x] = 0;
}
__global__ void k_count(const float* __restrict__ x) {
    __shared__ int hist[NHEADS];
    if (threadIdx.x < NHEADS) hist[threadIdx.x] = 0;
    __syncthreads();
    int b = blockIdx.x * blockDim.x + threadIdx.x;
    if (b < BATCH) atomicAdd(&hist[head_of(x + (size_t)b * XSTRIDE)], 1);
    __syncthreads();
    if (threadIdx.x < NHEADS) atomicAdd(&g_counts[threadIdx.x], hist[threadIdx.x]);
}
// scan offsets + build tile map + zero tile-done flags
__global__ void k_scanzero() {
    int t = threadIdx.x;
    if (t < MAXTILES) g_tiledone[t] = 0;
    if (t == 0) {
        int s = 0, n = 0;
        for (int h = 0; h < NHEADS; h++) {
            int c = g_counts[h];
            g_off[h] = s; g_cursor[h] = s; s += c;
            int nt = (c + 127) / 128;
            for (int m = 0; m < nt && n < MAXTILES; m++)
                g_tilemap[n++] = (h << 16) | m;
        }
        g_ntiles = n;
    }
}
__global__ void k_fillperm(const float* __restrict__ x) {
    int b = blockIdx.x * blockDim.x + threadIdx.x;
    if (b >= BATCH) return;
    int pos = atomicAdd(&g_cursor[head_of(x + (size_t)b * XSTRIDE)], 1);
    g_permsrc[pos] = b;
}
// convert rows [rowBeg, rowBeg+rowCnt) of x features to fp16
__global__ void k_convert(const float* __restrict__ x, int rowBeg, int rowCnt) {
    int idx = (blockIdx.x * blockDim.x + threadIdx.x) * 2;
    if (idx >= rowCnt * DFEAT) return;
    int b = rowBeg + idx / DFEAT, c = idx % DFEAT;
    const float* xr = x + (size_t)b * XSTRIDE + NBITS + c;
    *(__half2*)(g_x + (size_t)b * DFEAT + c) =
        __halves2half2(__float2half(xr[0]), __float2half(xr[1]));
}
__global__ void k_transpose(const float* __restrict__ in, __half* __restrict__ outp,
                            int R, int C) {
    __shared__ float t[32][33];
    int z = blockIdx.z;
    const float* src = in + (size_t)z * R * C;
    size_t ob = (size_t)z * R * C;
    int c0 = blockIdx.x * 32, r0 = blockIdx.y * 32;
    int tx = threadIdx.x, ty = threadIdx.y;
    #pragma unroll
    for (int i = 0; i < 32; i += 8)
        t[ty + i][tx] = src[(size_t)(r0 + ty + i) * C + c0 + tx];
    __syncthreads();
    #pragma unroll
    for (int i = 0; i < 32; i += 8)
        outp[ob + (size_t)(c0 + ty + i) * R + r0 + tx] = __float2half(t[tx][ty + i]);
}

// ---------------- shared GEMM mainloop (macro-free inline) --------------------
struct GemmCtx {
    uint32_t sbase;
    const __half* A;        // row base (direct rows) — used when rowidx==nullptr
    const int* rowidx;      // smem gather table or nullptr
    const __half* Bmat;     // weight [head][N][K] base (already head-offset)
    int K, N, m0, mValid;
    int n0;
};

// ---------------- GEMM1: dense, A = g_x ---------------------------------------
__global__ __launch_bounds__(256, 1)
void gemm1_hmma(const __half* __restrict__ A, const __half* __restrict__ B,
                const float* __restrict__ bias, __half* __restrict__ Ch,
                int mbase)
{
    extern __shared__ char dsm_raw[];
    char* dsm = (char*)(((uintptr_t)dsm_raw + 1023) & ~(uintptr_t)1023);
    const uint32_t sbase = smem_u32(dsm);
    const int K = DFEAT, N = DBASE;
    const int m0 = (mbase + blockIdx.y) * 128;
    const int n0 = blockIdx.x * BN;
    const int tid = threadIdx.x, wid = tid >> 5, lane = tid & 31;
    const int NC = K / KC;

    auto load_stage = [&](int c) {
        const int kt = c * KC;
        const uint32_t sb = sbase + (c & 1) * STAGE_B;
        #pragma unroll
        for (int j = 0; j < 24; ++j) {
            int idx = j * 256 + tid;
            const __half* gp; uint32_t dst;
            if (idx < 2048) {
                int r = idx >> 4, q = idx & 15;
                dst = sb + OFF_A + (uint32_t)(r * PITCH + q * 16);
                gp = A + (size_t)(m0 + r) * K + kt + q * 8;
            } else {
                int t2 = idx - 2048;
                int r = t2 >> 4, q = t2 & 15;
                dst = sb + OFF_B + (uint32_t)(r * PITCH + q * 16);
                gp = B + (size_t)(n0 + r) * K + kt + q * 8;
            }
            CP_ASYNC16(dst, gp);
        }
    };
    load_stage(0); CP_COMMIT();

    const int wm = (wid >> 2) * 64, wn = (wid & 3) * 64;
    const int gid = lane >> 2, tig = lane & 3;
    float acc[4][8][4];
    #pragma unroll
    for (int mg = 0; mg < 4; mg++)
        #pragma unroll
        for (int ng = 0; ng < 8; ng++)
            #pragma unroll
            for (int v = 0; v < 4; v++) acc[mg][ng][v] = 0.0f;

    for (int c = 0; c < NC; ++c) {
        if (c + 1 < NC) load_stage(c + 1);
        CP_COMMIT(); CP_WAIT1(); __syncthreads();
        const uint32_t sb = sbase + (c & 1) * STAGE_B;
        const uint32_t sA = sb + OFF_A, sB = sb + OFF_B;
        #pragma unroll
        for (int kk = 0; kk < KC; kk += 16) {
            const uint32_t kb = (uint32_t)(kk * 2 + tig * 4);
            uint32_t af[4][4], bfr[8][2];
            #pragma unroll
            for (int mg = 0; mg < 4; mg++) {
                const uint32_t p0 = (uint32_t)((wm + mg * 16 + gid) * PITCH) + kb;
                af[mg][0] = lds32(sA + p0);
                af[mg][1] = lds32(sA + p0 + 8 * PITCH);
                af[mg][2] = lds32(sA + p0 + 16);
                af[mg][3] = lds32(sA + p0 + 8 * PITCH + 16);
            }
            #pragma unroll
            for (int ng = 0; ng < 8; ng++) {
                const uint32_t p0 = (uint32_t)((wn + ng * 8 + gid) * PITCH) + kb;
                bfr[ng][0] = lds32(sB + p0);
                bfr[ng][1] = lds32(sB + p0 + 16);
            }
            #pragma unroll
            for (int mg = 0; mg < 4; mg++)
                #pragma unroll
                for (int ng = 0; ng < 8; ng++)
                    mma16816(acc[mg][ng], af[mg], bfr[ng]);
        }
        __syncthreads();
    }
    CP_WAIT0();

    const float* bp = bias + n0;
    #pragma unroll
    for (int mg = 0; mg < 4; mg++)
        #pragma unroll
        for (int half = 0; half < 2; half++) {
            const int gm = m0 + wm + mg * 16 + gid + half * 8;
            #pragma unroll
            for (int ng = 0; ng < 8; ng++) {
                const int col = wn + ng * 8 + tig * 2;
                float v0 = fmaxf(acc[mg][ng][half * 2]     + __ldg(bp + col), 0.0f);
                float v1 = fmaxf(acc[mg][ng][half * 2 + 1] + __ldg(bp + col + 1), 0.0f);
                *(__half2*)(Ch + (size_t)gm * N + n0 + col) =
                    __halves2half2(__float2half(v0), __float2half(v1));
            }
        }
}

// ---------------- fused GEMM2+GEMM3 --------------------------------------------
// blockIdx.x in [0, G2_CTAS): GEMM2 (gather A from g_b via permsrc, relu->g_h,
//   release g_tiledone[t]). blockIdx.x in [G2_CTAS, +G3_CTAS): GEMM3 (spin on
//   g_tiledone[t]==4, A = g_h rows, fp32 scatter to out via permsrc).
__global__ __launch_bounds__(256, 1)
void gemm23_fused(const __half* __restrict__ Bact, const __half* __restrict__ W1,
                  const __half* __restrict__ W2, const float* __restrict__ bh1,
                  const float* __restrict__ bh2, __half* __restrict__ Hh,
                  float* __restrict__ out)
{
    extern __shared__ char dsm_raw[];
    __shared__ int s_rowidx[128];
    char* dsm = (char*)(((uintptr_t)dsm_raw + 1023) & ~(uintptr_t)1023);
    const uint32_t sbase = smem_u32(dsm);
    const int tid = threadIdx.x, wid = tid >> 5, lane = tid & 31;

    const bool isG2 = (int)blockIdx.x < G2_CTAS;
    int t, n0, N;
    if (isG2) { int id = blockIdx.x;            t = id >> 2; n0 = (id & 3) * BN; N = DH; }
    else      { int id = blockIdx.x - G2_CTAS;  t = id >> 1; n0 = (id & 1) * BN; N = DOUT; }
    if (t >= g_ntiles) return;

    const int e = g_tilemap[t];
    const int head = e >> 16, mtile = e & 0xFFFF;
    const int rowBeg = g_off[head], cnt = g_counts[head];
    const int m0 = rowBeg + mtile * 128;
    const int mValid = min(128, cnt - mtile * 128);
    const int rowEnd = rowBeg + cnt;
    const int K = DBASE; // == DH
    const int NC = K / KC;

    if (isG2) {
        if (tid < 128) {
            int p = m0 + tid;
            s_rowidx[tid] = g_permsrc[p < rowEnd ? p : rowEnd - 1];
        }
        __syncthreads();
    } else {
        // wait for the 4 GEMM2 producer CTAs of this m-tile
        if (tid == 0) {
            const int* cp = &g_tiledone[t];
            int v;
            while (true) {
                asm volatile("ld.global.cg.b32 %0, [%1];" : "=r"(v) : "l"(cp));
                if (v >= 4) break;
                asm volatile("nanosleep.u32 256;");
            }
        }
        __syncthreads();
        __threadfence();
    }

    const __half* A    = isG2 ? Bact : Hh;
    const __half* Bmat = (isG2 ? W1 : W2) + (size_t)head * N * K;

    auto load_stage = [&](int c) {
        const int kt = c * KC;
        const uint32_t sb = sbase + (c & 1) * STAGE_B;
        #pragma unroll
        for (int j = 0; j < 24; ++j) {
            int idx = j * 256 + tid;
            const __half* gp; uint32_t dst;
            if (idx < 2048) {
                int r = idx >> 4, q = idx & 15;
                dst = sb + OFF_A + (uint32_t)(r * PITCH + q * 16);
                int rowg = isG2 ? s_rowidx[r] : min(m0 + r, rowEnd - 1);
                gp = A + (size_t)rowg * K + kt + q * 8;
            } else {
                int t2 = idx - 2048;
                int r = t2 >> 4, q = t2 & 15;
                dst = sb + OFF_B + (uint32_t)(r * PITCH + q * 16);
                gp = Bmat + (size_t)(n0 + r) * K + kt + q * 8;
            }
            CP_ASYNC16(dst, gp);
        }
    };
    load_stage(0); CP_COMMIT();

    const int wm = (wid >> 2) * 64, wn = (wid & 3) * 64;
    const int gid = lane >> 2, tig = lane & 3;
    float acc[4][8][4];
    #pragma unroll
    for (int mg = 0; mg < 4; mg++)
        #pragma unroll
        for (int ng = 0; ng < 8; ng++)
            #pragma unroll
            for (int v = 0; v < 4; v++) acc[mg][ng][v] = 0.0f;

    for (int c = 0; c < NC; ++c) {
        if (c + 1 < NC) load_stage(c + 1);
        CP_COMMIT(); CP_WAIT1(); __syncthreads();
        const uint32_t sb = sbase + (c & 1) * STAGE_B;
        const uint32_t sA = sb + OFF_A, sB = sb + OFF_B;
        #pragma unroll
        for (int kk = 0; kk < KC; kk += 16) {
            const uint32_t kb = (uint32_t)(kk * 2 + tig * 4);
            uint32_t af[4][4], bfr[8][2];
            #pragma unroll
            for (int mg = 0; mg < 4; mg++) {
                const uint32_t p0 = (uint32_t)((wm + mg * 16 + gid) * PITCH) + kb;
                af[mg][0] = lds32(sA + p0);
                af[mg][1] = lds32(sA + p0 + 8 * PITCH);
                af[mg][2] = lds32(sA + p0 + 16);
                af[mg][3] = lds32(sA + p0 + 8 * PITCH + 16);
            }
            #pragma unroll
            for (int ng = 0; ng < 8; ng++) {
                const uint32_t p0 = (uint32_t)((wn + ng * 8 + gid) * PITCH) + kb;
                bfr[ng][0] = lds32(sB + p0);
                bfr[ng][1] = lds32(sB + p0 + 16);
            }
            #pragma unroll
            for (int mg = 0; mg < 4; mg++)
                #pragma unroll
                for (int ng = 0; ng < 8; ng++)
                    mma16816(acc[mg][ng], af[mg], bfr[ng]);
        }
        __syncthreads();
    }
    CP_WAIT0();

    const float* bp = (isG2 ? bh1 : bh2) + (size_t)head * N + n0;
    #pragma unroll
    for (int mg = 0; mg < 4; mg++)
        #pragma unroll
        for (int half = 0; half < 2; half++) {
            const int mrow = wm + mg * 16 + gid + half * 8;
            if (mrow >= mValid) continue;
            const int gm = m0 + mrow;
            #pragma unroll
            for (int ng = 0; ng < 8; ng++) {
                const int col = wn + ng * 8 + tig * 2;
                float v0 = acc[mg][ng][half * 2]     + __ldg(bp + col);
                float v1 = acc[mg][ng][half * 2 + 1] + __ldg(bp + col + 1);
                if (isG2) {
                    v0 = fmaxf(v0, 0.0f); v1 = fmaxf(v1, 0.0f);
                    *(__half2*)(Hh + (size_t)gm * N + n0 + col) =
                        __halves2half2(__float2half(v0), __float2half(v1));
                } else {
                    const int orow = g_permsrc[gm];
                    *(float2*)(out + (size_t)orow * N + n0 + col) = make_float2(v0, v1);
                }
            }
        }

    if (isG2) {   // release this m-tile for GEMM3 consumers
        __threadfence();
        __syncthreads();
        if (tid == 0) atomicAdd(&g_tiledone[t], 1);
    }
}

// ---------------- host launcher -------------------------------------------------
extern "C" void kernel_launch(void* const* d_in, const int* in_sizes, int n_in,
                              void* d_out, int out_size)
{
    (void)in_sizes; (void)n_in; (void)out_size;
    const float* x   = (const float*)d_in[0];
    const float* Wb  = (const float*)d_in[1];
    const float* bb  = (const float*)d_in[2];
    const float* Wh1 = (const float*)d_in[3];
    const float* bh1 = (const float*)d_in[4];
    const float* Wh2 = (const float*)d_in[5];
    const float* bh2 = (const float*)d_in[6];
    float* out = (float*)d_out;

    void *p_x, *p_b, *p_h, *p_wbt, *p_w1t, *p_w2t;
    cudaGetSymbolAddress(&p_x, g_x);
    cudaGetSymbolAddress(&p_b, g_b);
    cudaGetSymbolAddress(&p_h, g_h);
    cudaGetSymbolAddress(&p_wbt, g_wbt);
    cudaGetSymbolAddress(&p_w1t, g_w1t);
    cudaGetSymbolAddress(&p_w2t, g_w2t);

    cudaFuncSetAttribute(gemm1_hmma,   cudaFuncAttributeMaxDynamicSharedMemorySize, DSMEM_BYTES);
    cudaFuncSetAttribute(gemm23_fused, cudaFuncAttributeMaxDynamicSharedMemorySize, DSMEM_BYTES);

    // ---- fork ----
    cudaEventRecord(s_fork, 0);
    cudaStreamWaitEvent(s_side, s_fork, 0);
    cudaStreamWaitEvent(s_rt,   s_fork, 0);
    cudaStreamWaitEvent(s_cv,   s_fork, 0);

    // side1: weight transposes
    k_transpose<<<dim3(DBASE / 32, DFEAT / 32, 1), dim3(32, 8), 0, s_side>>>(
        Wb, (__half*)p_wbt, DFEAT, DBASE);
    cudaEventRecord(s_ewb, s_side);
    k_transpose<<<dim3(DH / 32, DBASE / 32, NHEADS), dim3(32, 8), 0, s_side>>>(
        Wh1, (__half*)p_w1t, DBASE, DH);
    cudaEventRecord(s_ew1, s_side);
    k_transpose<<<dim3(DOUT / 32, DH / 32, NHEADS), dim3(32, 8), 0, s_side>>>(
        Wh2, (__half*)p_w2t, DH, DOUT);
    cudaEventRecord(s_ew2, s_side);

    // side2: routing (index-only)
    k_zeroc<<<1, 32, 0, s_rt>>>();
    k_count<<<BATCH / 256, 256, 0, s_rt>>>(x);
    k_scanzero<<<1, MAXTILES, 0, s_rt>>>();
    k_fillperm<<<BATCH / 256, 256, 0, s_rt>>>(x);
    cudaEventRecord(s_ert, s_rt);

    // side3: second half of the x conversion
    k_convert<<<(4096 * DFEAT / 2 + 255) / 256, 256, 0, s_cv>>>(x, 4096, 4096);
    cudaEventRecord(s_ecvb, s_cv);

    // main: first half convert -> GEMM1 halves -> fused GEMM2+3
    k_convert<<<(4096 * DFEAT / 2 + 255) / 256, 256>>>(x, 0, 4096);

    cudaStreamWaitEvent(0, s_ewb, 0);
    gemm1_hmma<<<dim3(DBASE / BN, 32, 1), 256, DSMEM_BYTES>>>(
        (const __half*)p_x, (const __half*)p_wbt, bb, (__half*)p_b, 0);
    cudaStreamWaitEvent(0, s_ecvb, 0);
    gemm1_hmma<<<dim3(DBASE / BN, 32, 1), 256, DSMEM_BYTES>>>(
        (const __half*)p_x, (const __half*)p_wbt, bb, (__half*)p_b, 32);

    cudaStreamWaitEvent(0, s_ert, 0);
    cudaStreamWaitEvent(0, s_ew1, 0);
    cudaStreamWaitEvent(0, s_ew2, 0);
    gemm23_fused<<<G2_CTAS + G3_CTAS, 256, DSMEM_BYTES>>>(
        (const __half*)p_b, (const __half*)p_w1t, (const __half*)p_w2t,
        bh1, bh2, (__half*)p_h, out);
}

// round 15
// speedup vs baseline: 1.0180x; 1.0180x over previous
#include <cuda_runtime.h>
#include <cuda_fp16.h>
#include <cstdint>

// ============================================================================
// MultiHeadNet, R15: R13 structure (wide grids, side-stream transposes and
// index-only routing, tile-mapped grouped GEMMs) + GEMM1 fuses the fp32->fp16
// conversion of x into its A-tile loader (k_convert eliminated from the
// critical path). HMMA fp16 core, 128x256 tile, KC=128, ~512 MAC/cyc/SM cap.
// ============================================================================

constexpr int BATCH  = 8192;
constexpr int NBITS  = 3;
constexpr int DFEAT  = 512;
constexpr int DBASE  = 1024;
constexpr int DH     = 1024;
constexpr int DOUT   = 512;
constexpr int NHEADS = 8;
constexpr int XSTRIDE = NBITS + DFEAT; // 515
constexpr int MAXTILES = 76;           // >= worst-case sum ceil(cnt_h/128)

constexpr int KC = 128;
constexpr int BN = 256;
constexpr int PITCH = 272;                          // 256 data + 16 pad
constexpr int A_PB = 128 * PITCH;                   // 34816
constexpr int B_PB = BN * PITCH;                    // 69632
constexpr int OFF_A = 0, OFF_B = A_PB;
constexpr int STAGE_B = A_PB + B_PB;                // 104448
constexpr int DSMEM_BYTES = 2 * STAGE_B + 1024;     // 209920

// ---------------- scratch (__device__ globals) -------------------------------
__device__ int g_counts[NHEADS];
__device__ int g_off[NHEADS];
__device__ int g_cursor[NHEADS];
__device__ int g_permsrc[BATCH];
__device__ int g_tilemap[MAXTILES];    // (head<<16) | mtile
__device__ int g_ntiles;

__device__ __half g_b[(size_t)BATCH * DBASE];            // original row order
__device__ __half g_h[(size_t)BATCH * DH];               // permuted (per-head)
__device__ __half g_wbt[(size_t)DBASE * DFEAT];          // [N][K]
__device__ __half g_w1t[(size_t)NHEADS * DH * DBASE];    // [h][N][K]
__device__ __half g_w2t[(size_t)NHEADS * DOUT * DH];     // [h][N][K]

// ---------------- streams + events (host-side, static init) ------------------
static cudaStream_t s_side = nullptr, s_rt = nullptr;
static cudaEvent_t s_fork = nullptr, s_ewb = nullptr, s_ew1 = nullptr,
                   s_ew2 = nullptr, s_ert = nullptr;
static struct SideInit {
    SideInit() {
        cudaStreamCreateWithFlags(&s_side, cudaStreamNonBlocking);
        cudaStreamCreateWithFlags(&s_rt,   cudaStreamNonBlocking);
        cudaEventCreateWithFlags(&s_fork, cudaEventDisableTiming);
        cudaEventCreateWithFlags(&s_ewb,  cudaEventDisableTiming);
        cudaEventCreateWithFlags(&s_ew1,  cudaEventDisableTiming);
        cudaEventCreateWithFlags(&s_ew2,  cudaEventDisableTiming);
        cudaEventCreateWithFlags(&s_ert,  cudaEventDisableTiming);
    }
} s_side_init;

// ---------------- PTX helpers -------------------------------------------------
__device__ __forceinline__ uint32_t smem_u32(const void* p) {
    uint32_t a;
    asm("{ .reg .u64 t; cvta.to.shared.u64 t, %1; cvt.u32.u64 %0, t; }" : "=r"(a) : "l"(p));
    return a;
}
#define CP_ASYNC16(saddr, gptr) \
    asm volatile("cp.async.cg.shared.global [%0], [%1], 16;" :: "r"(saddr), "l"(gptr))
#define CP_COMMIT() asm volatile("cp.async.commit_group;" ::: "memory")
#define CP_WAIT1()  asm volatile("cp.async.wait_group 1;" ::: "memory")
#define CP_WAIT0()  asm volatile("cp.async.wait_group 0;" ::: "memory")

__device__ __forceinline__ uint32_t lds32(uint32_t saddr) {
    uint32_t v;
    asm volatile("ld.shared.b32 %0, [%1];" : "=r"(v) : "r"(saddr));
    return v;
}
__device__ __forceinline__ void mma16816(float* c, const uint32_t* a, const uint32_t* b) {
    asm volatile("mma.sync.aligned.m16n8k16.row.col.f32.f16.f16.f32 "
        "{%0,%1,%2,%3}, {%4,%5,%6,%7}, {%8,%9}, {%0,%1,%2,%3};"
        : "+f"(c[0]), "+f"(c[1]), "+f"(c[2]), "+f"(c[3])
        : "r"(a[0]), "r"(a[1]), "r"(a[2]), "r"(a[3]), "r"(b[0]), "r"(b[1]));
}

// ---------------- prep kernels -------------------------------------------------
__device__ __forceinline__ int head_of(const float* xr) {
    return (xr[0] > 0.5f ? 1 : 0) | (xr[1] > 0.5f ? 2 : 0) | (xr[2] > 0.5f ? 4 : 0);
}
__global__ void k_zeroc() {
    if (threadIdx.x < NHEADS) g_counts[threadIdx.x] = 0;
}
__global__ void k_count(const float* __restrict__ x) {
    __shared__ int hist[NHEADS];
    if (threadIdx.x < NHEADS) hist[threadIdx.x] = 0;
    __syncthreads();
    int b = blockIdx.x * blockDim.x + threadIdx.x;
    if (b < BATCH) atomicAdd(&hist[head_of(x + (size_t)b * XSTRIDE)], 1);
    __syncthreads();
    if (threadIdx.x < NHEADS) atomicAdd(&g_counts[threadIdx.x], hist[threadIdx.x]);
}
__global__ void k_scanzero() {
    if (threadIdx.x == 0) {
        int s = 0, t = 0;
        for (int h = 0; h < NHEADS; h++) {
            int c = g_counts[h];
            g_off[h] = s; g_cursor[h] = s; s += c;
            int nt = (c + 127) / 128;
            for (int m = 0; m < nt && t < MAXTILES; m++)
                g_tilemap[t++] = (h << 16) | m;
        }
        g_ntiles = t;
    }
}
__global__ void k_fillperm(const float* __restrict__ x) {
    int b = blockIdx.x * blockDim.x + threadIdx.x;
    if (b >= BATCH) return;
    int pos = atomicAdd(&g_cursor[head_of(x + (size_t)b * XSTRIDE)], 1);
    g_permsrc[pos] = b;
}
__global__ void k_transpose(const float* __restrict__ in, __half* __restrict__ outp,
                            int R, int C) {
    __shared__ float t[32][33];
    int z = blockIdx.z;
    const float* src = in + (size_t)z * R * C;
    size_t ob = (size_t)z * R * C;
    int c0 = blockIdx.x * 32, r0 = blockIdx.y * 32;
    int tx = threadIdx.x, ty = threadIdx.y;
    #pragma unroll
    for (int i = 0; i < 32; i += 8)
        t[ty + i][tx] = src[(size_t)(r0 + ty + i) * C + c0 + tx];
    __syncthreads();
    #pragma unroll
    for (int i = 0; i < 32; i += 8)
        outp[ob + (size_t)(c0 + ty + i) * R + r0 + tx] = __float2half(t[tx][ty + i]);
}

// ---------------- GEMM1: A = x (fp32, fused convert), B = wbt ------------------
__global__ __launch_bounds__(256, 1)
void gemm1_fused(const float* __restrict__ x, const __half* __restrict__ B,
                 const float* __restrict__ bias, __half* __restrict__ Ch)
{
    extern __shared__ char dsm_raw[];
    char* dsm = (char*)(((uintptr_t)dsm_raw + 1023) & ~(uintptr_t)1023);
    const uint32_t sbase = smem_u32(dsm);
    const int K = DFEAT, N = DBASE;
    const int m0 = blockIdx.y * 128;
    const int n0 = blockIdx.x * BN;
    const int tid = threadIdx.x, wid = tid >> 5, lane = tid & 31;
    const int NC = K / KC;   // 4

    // B: cp.async (4096 16B chunks / 256 thr = 16 iters)
    auto load_B = [&](int c) {
        const int kt = c * KC;
        const uint32_t sb = sbase + (c & 1) * STAGE_B;
        #pragma unroll
        for (int j = 0; j < 16; ++j) {
            int idx = j * 256 + tid;
            int r = idx >> 4, q = idx & 15;
            uint32_t dst = sb + OFF_B + (uint32_t)(r * PITCH + q * 16);
            CP_ASYNC16(dst, B + (size_t)(n0 + r) * K + kt + q * 8);
        }
    };
    // A: fp32 loads + convert + STS (8192 half2 words / 256 thr = 32 iters)
    auto load_A = [&](int c) {
        const int kt = c * KC;
        char* sb = dsm + (c & 1) * STAGE_B + OFF_A;
        #pragma unroll 8
        for (int j = 0; j < 32; ++j) {
            int idx = j * 256 + tid;
            int r = idx >> 6, w = idx & 63;
            const float* xp = x + (size_t)(m0 + r) * XSTRIDE + NBITS + kt + 2 * w;
            __half2 hv = __floats2half2_rn(__ldg(xp), __ldg(xp + 1));
            *(__half2*)(sb + r * PITCH + w * 4) = hv;
        }
    };

    load_B(0); CP_COMMIT(); load_A(0);

    const int wm = (wid >> 2) * 64, wn = (wid & 3) * 64;
    const int gid = lane >> 2, tig = lane & 3;
    float acc[4][8][4];
    #pragma unroll
    for (int mg = 0; mg < 4; mg++)
        #pragma unroll
        for (int ng = 0; ng < 8; ng++)
            #pragma unroll
            for (int v = 0; v < 4; v++) acc[mg][ng][v] = 0.0f;

    for (int c = 0; c < NC; ++c) {
        if (c + 1 < NC) { load_B(c + 1); CP_COMMIT(); load_A(c + 1); }
        else CP_COMMIT();
        CP_WAIT1();
        __syncthreads();

        const uint32_t sb = sbase + (c & 1) * STAGE_B;
        const uint32_t sA = sb + OFF_A, sB = sb + OFF_B;
        #pragma unroll
        for (int kk = 0; kk < KC; kk += 16) {
            const uint32_t kb = (uint32_t)(kk * 2 + tig * 4);
            uint32_t af[4][4], bfr[8][2];
            #pragma unroll
            for (int mg = 0; mg < 4; mg++) {
                const uint32_t p0 = (uint32_t)((wm + mg * 16 + gid) * PITCH) + kb;
                af[mg][0] = lds32(sA + p0);
                af[mg][1] = lds32(sA + p0 + 8 * PITCH);
                af[mg][2] = lds32(sA + p0 + 16);
                af[mg][3] = lds32(sA + p0 + 8 * PITCH + 16);
            }
            #pragma unroll
            for (int ng = 0; ng < 8; ng++) {
                const uint32_t p0 = (uint32_t)((wn + ng * 8 + gid) * PITCH) + kb;
                bfr[ng][0] = lds32(sB + p0);
                bfr[ng][1] = lds32(sB + p0 + 16);
            }
            #pragma unroll
            for (int mg = 0; mg < 4; mg++)
                #pragma unroll
                for (int ng = 0; ng < 8; ng++)
                    mma16816(acc[mg][ng], af[mg], bfr[ng]);
        }
        __syncthreads();
    }
    CP_WAIT0();

    const float* bp = bias + n0;
    #pragma unroll
    for (int mg = 0; mg < 4; mg++)
        #pragma unroll
        for (int half = 0; half < 2; half++) {
            const int gm = m0 + wm + mg * 16 + gid + half * 8;
            #pragma unroll
            for (int ng = 0; ng < 8; ng++) {
                const int col = wn + ng * 8 + tig * 2;
                float v0 = fmaxf(acc[mg][ng][half * 2]     + __ldg(bp + col), 0.0f);
                float v1 = fmaxf(acc[mg][ng][half * 2 + 1] + __ldg(bp + col + 1), 0.0f);
                *(__half2*)(Ch + (size_t)gm * N + n0 + col) =
                    __halves2half2(__float2half(v0), __float2half(v1));
            }
        }
}

// ---------------- grouped GEMM (GEMM2 / GEMM3), tile-mapped --------------------
// CMODE 0: relu -> fp16 contiguous rows (GEMM2, gather A via permsrc).
// CMODE 1: fp32 scatter via permsrc (GEMM3, contiguous A).
template<int CMODE, int GATHER>
__global__ __launch_bounds__(256, 1)
void gemm_hmma(const __half* __restrict__ A, const __half* __restrict__ B,
               const float* __restrict__ bias,
               __half* __restrict__ Ch, float* __restrict__ Cf,
               int K, int N)
{
    extern __shared__ char dsm_raw[];
    __shared__ int s_rowidx[128];
    char* dsm = (char*)(((uintptr_t)dsm_raw + 1023) & ~(uintptr_t)1023);
    const uint32_t sbase = smem_u32(dsm);

    if ((int)blockIdx.y >= g_ntiles) return;
    const int e = g_tilemap[blockIdx.y];
    const int head = e >> 16, mtile = e & 0xFFFF;
    const int rowBeg = g_off[head], cnt = g_counts[head];
    const int m0 = rowBeg + mtile * 128;
    const int mValid = min(128, cnt - mtile * 128);
    const int rowEnd = rowBeg + cnt;
    const int n0  = blockIdx.x * BN;
    const int tid = threadIdx.x, wid = tid >> 5, lane = tid & 31;
    const int NC = K / KC;

    if (GATHER) {
        if (tid < 128) {
            int p = m0 + tid;
            s_rowidx[tid] = g_permsrc[p < rowEnd ? p : rowEnd - 1];
        }
        __syncthreads();
    }

    auto load_stage = [&](int c) {
        const int kt = c * KC;
        const uint32_t sb = sbase + (c & 1) * STAGE_B;
        #pragma unroll
        for (int j = 0; j < 24; ++j) {
            int idx = j * 256 + tid;
            const __half* gp; uint32_t dst;
            if (idx < 2048) {
                int r = idx >> 4, q = idx & 15;
                dst = sb + OFF_A + (uint32_t)(r * PITCH + q * 16);
                int rowg = GATHER ? s_rowidx[r] : min(m0 + r, rowEnd - 1);
                gp = A + (size_t)rowg * K + kt + q * 8;
            } else {
                int t2 = idx - 2048;
                int r = t2 >> 4, q = t2 & 15;
                dst = sb + OFF_B + (uint32_t)(r * PITCH + q * 16);
                gp = B + ((size_t)head * N + n0 + r) * K + kt + q * 8;
            }
            CP_ASYNC16(dst, gp);
        }
    };

    load_stage(0); CP_COMMIT();

    const int wm = (wid >> 2) * 64, wn = (wid & 3) * 64;
    const int gid = lane >> 2, tig = lane & 3;
    float acc[4][8][4];
    #pragma unroll
    for (int mg = 0; mg < 4; mg++)
        #pragma unroll
        for (int ng = 0; ng < 8; ng++)
            #pragma unroll
            for (int v = 0; v < 4; v++) acc[mg][ng][v] = 0.0f;

    for (int c = 0; c < NC; ++c) {
        if (c + 1 < NC) load_stage(c + 1);
        CP_COMMIT(); CP_WAIT1(); __syncthreads();
        const uint32_t sb = sbase + (c & 1) * STAGE_B;
        const uint32_t sA = sb + OFF_A, sB = sb + OFF_B;
        #pragma unroll
        for (int kk = 0; kk < KC; kk += 16) {
            const uint32_t kb = (uint32_t)(kk * 2 + tig * 4);
            uint32_t af[4][4], bfr[8][2];
            #pragma unroll
            for (int mg = 0; mg < 4; mg++) {
                const uint32_t p0 = (uint32_t)((wm + mg * 16 + gid) * PITCH) + kb;
                af[mg][0] = lds32(sA + p0);
                af[mg][1] = lds32(sA + p0 + 8 * PITCH);
                af[mg][2] = lds32(sA + p0 + 16);
                af[mg][3] = lds32(sA + p0 + 8 * PITCH + 16);
            }
            #pragma unroll
            for (int ng = 0; ng < 8; ng++) {
                const uint32_t p0 = (uint32_t)((wn + ng * 8 + gid) * PITCH) + kb;
                bfr[ng][0] = lds32(sB + p0);
                bfr[ng][1] = lds32(sB + p0 + 16);
            }
            #pragma unroll
            for (int mg = 0; mg < 4; mg++)
                #pragma unroll
                for (int ng = 0; ng < 8; ng++)
                    mma16816(acc[mg][ng], af[mg], bfr[ng]);
        }
        __syncthreads();
    }
    CP_WAIT0();

    const float* bp = bias + (size_t)head * N + n0;
    #pragma unroll
    for (int mg = 0; mg < 4; mg++)
        #pragma unroll
        for (int half = 0; half < 2; half++) {
            const int mrow = wm + mg * 16 + gid + half * 8;
            if (mrow >= mValid) continue;
            const int gm = m0 + mrow;
            #pragma unroll
            for (int ng = 0; ng < 8; ng++) {
                const int col = wn + ng * 8 + tig * 2;
                float v0 = acc[mg][ng][half * 2]     + __ldg(bp + col);
                float v1 = acc[mg][ng][half * 2 + 1] + __ldg(bp + col + 1);
                if (CMODE == 0) {
                    v0 = fmaxf(v0, 0.0f); v1 = fmaxf(v1, 0.0f);
                    *(__half2*)(Ch + (size_t)gm * N + n0 + col) =
                        __halves2half2(__float2half(v0), __float2half(v1));
                } else {
                    const int orow = g_permsrc[gm];
                    *(float2*)(Cf + (size_t)orow * N + n0 + col) = make_float2(v0, v1);
                }
            }
        }
}

// ---------------- host launcher -------------------------------------------------
extern "C" void kernel_launch(void* const* d_in, const int* in_sizes, int n_in,
                              void* d_out, int out_size)
{
    (void)in_sizes; (void)n_in; (void)out_size;
    const float* x   = (const float*)d_in[0];
    const float* Wb  = (const float*)d_in[1];
    const float* bb  = (const float*)d_in[2];
    const float* Wh1 = (const float*)d_in[3];
    const float* bh1 = (const float*)d_in[4];
    const float* Wh2 = (const float*)d_in[5];
    const float* bh2 = (const float*)d_in[6];
    float* out = (float*)d_out;

    void *p_b, *p_h, *p_wbt, *p_w1t, *p_w2t;
    cudaGetSymbolAddress(&p_b, g_b);
    cudaGetSymbolAddress(&p_h, g_h);
    cudaGetSymbolAddress(&p_wbt, g_wbt);
    cudaGetSymbolAddress(&p_w1t, g_w1t);
    cudaGetSymbolAddress(&p_w2t, g_w2t);

    cudaFuncSetAttribute(gemm1_fused, cudaFuncAttributeMaxDynamicSharedMemorySize, DSMEM_BYTES);
    cudaFuncSetAttribute((const void*)gemm_hmma<0,1>, cudaFuncAttributeMaxDynamicSharedMemorySize, DSMEM_BYTES);
    cudaFuncSetAttribute((const void*)gemm_hmma<1,0>, cudaFuncAttributeMaxDynamicSharedMemorySize, DSMEM_BYTES);

    // ---- fork ----
    cudaEventRecord(s_fork, 0);
    cudaStreamWaitEvent(s_side, s_fork, 0);
    cudaStreamWaitEvent(s_rt,   s_fork, 0);

    // side1: weight transposes
    k_transpose<<<dim3(DBASE / 32, DFEAT / 32, 1), dim3(32, 8), 0, s_side>>>(
        Wb, (__half*)p_wbt, DFEAT, DBASE);
    cudaEventRecord(s_ewb, s_side);
    k_transpose<<<dim3(DH / 32, DBASE / 32, NHEADS), dim3(32, 8), 0, s_side>>>(
        Wh1, (__half*)p_w1t, DBASE, DH);
    cudaEventRecord(s_ew1, s_side);
    k_transpose<<<dim3(DOUT / 32, DH / 32, NHEADS), dim3(32, 8), 0, s_side>>>(
        Wh2, (__half*)p_w2t, DH, DOUT);
    cudaEventRecord(s_ew2, s_side);

    // side2: routing (index-only; overlaps GEMM1)
    k_zeroc<<<1, 32, 0, s_rt>>>();
    k_count<<<BATCH / 256, 256, 0, s_rt>>>(x);
    k_scanzero<<<1, 32, 0, s_rt>>>();
    k_fillperm<<<BATCH / 256, 256, 0, s_rt>>>(x);
    cudaEventRecord(s_ert, s_rt);

    // main: GEMM1 (fused convert) -> GEMM2 -> GEMM3
    cudaStreamWaitEvent(0, s_ewb, 0);
    gemm1_fused<<<dim3(DBASE / BN, BATCH / 128, 1), 256, DSMEM_BYTES>>>(
        x, (const __half*)p_wbt, bb, (__half*)p_b);

    cudaStreamWaitEvent(0, s_ert, 0);
    cudaStreamWaitEvent(0, s_ew1, 0);
    gemm_hmma<0,1><<<dim3(DH / BN, MAXTILES, 1), 256, DSMEM_BYTES>>>(
        (const __half*)p_b, (const __half*)p_w1t,
        bh1, (__half*)p_h, nullptr, DBASE, DH);

    cudaStreamWaitEvent(0, s_ew2, 0);
    gemm_hmma<1,0><<<dim3(DOUT / BN, MAXTILES, 1), 256, DSMEM_BYTES>>>(
        (const __half*)p_h, (const __half*)p_w2t,
        bh2, nullptr, out, DH, DOUT);
}

// round 17
// speedup vs baseline: 1.0653x; 1.0465x over previous
#include <cuda_runtime.h>
#include <cuda_fp16.h>
#include <cstdint>

// ============================================================================
// MultiHeadNet, R17: R13 baseline + GEMM1 reads x directly, staging A as fp32
// through 4-BYTE cp.async (x rows are only 4B-aligned: stride 515 floats).
// Convert fp32->fp16 at fragment load (ld.shared.v2.f32 + cvt.rn.f16x2).
// GEMM2/3 unchanged (tile-mapped, KC=128). HMMA fp16, ~512 MAC/cyc/SM cap.
// ============================================================================

constexpr int BATCH  = 8192;
constexpr int NBITS  = 3;
constexpr int DFEAT  = 512;
constexpr int DBASE  = 1024;
constexpr int DH     = 1024;
constexpr int DOUT   = 512;
constexpr int NHEADS = 8;
constexpr int XSTRIDE = NBITS + DFEAT; // 515
constexpr int MAXTILES = 76;

// grouped GEMM (GEMM2/3) tiling — R13 values
constexpr int KC = 128;
constexpr int BN = 256;
constexpr int PITCH = 272;                          // 256B data + 16 pad
constexpr int A_PB = 128 * PITCH;                   // 34816
constexpr int B_PB = BN * PITCH;                    // 69632
constexpr int OFF_A = 0, OFF_B = A_PB;
constexpr int STAGE_B = A_PB + B_PB;                // 104448
constexpr int DSMEM_BYTES = 2 * STAGE_B + 1024;     // 209920

// GEMM1 tiling: KC1=64; A tile fp32 (128 x 64 f32, pitch 272B),
// B tile fp16 (256 x 64 f16, pitch 144B)
constexpr int KC1 = 64;
constexpr int PITCH_A32 = 272;
constexpr int PITCH_B16 = 144;
constexpr int A1_PB = 128 * PITCH_A32;              // 34816
constexpr int B1_PB = BN * PITCH_B16;               // 36864
constexpr int OFF1_A = 0, OFF1_B = A1_PB;
constexpr int STAGE1_B = A1_PB + B1_PB;             // 71680
constexpr int DSMEM1_BYTES = 2 * STAGE1_B + 1024;   // 144384

// ---------------- scratch (__device__ globals) -------------------------------
__device__ int g_counts[NHEADS];
__device__ int g_off[NHEADS];
__device__ int g_cursor[NHEADS];
__device__ int g_permsrc[BATCH];
__device__ int g_tilemap[MAXTILES];    // (head<<16) | mtile
__device__ int g_ntiles;

__device__ __half g_b[(size_t)BATCH * DBASE];            // original row order
__device__ __half g_h[(size_t)BATCH * DH];               // permuted (per-head)
__device__ __half g_wbt[(size_t)DBASE * DFEAT];          // [N][K]
__device__ __half g_w1t[(size_t)NHEADS * DH * DBASE];    // [h][N][K]
__device__ __half g_w2t[(size_t)NHEADS * DOUT * DH];     // [h][N][K]

// ---------------- streams + events (host-side, static init) ------------------
static cudaStream_t s_side = nullptr, s_rt = nullptr;
static cudaEvent_t s_fork = nullptr, s_ewb = nullptr, s_ew1 = nullptr,
                   s_ew2 = nullptr, s_ert = nullptr;
static struct SideInit {
    SideInit() {
        cudaStreamCreateWithFlags(&s_side, cudaStreamNonBlocking);
        cudaStreamCreateWithFlags(&s_rt,   cudaStreamNonBlocking);
        cudaEventCreateWithFlags(&s_fork, cudaEventDisableTiming);
        cudaEventCreateWithFlags(&s_ewb,  cudaEventDisableTiming);
        cudaEventCreateWithFlags(&s_ew1,  cudaEventDisableTiming);
        cudaEventCreateWithFlags(&s_ew2,  cudaEventDisableTiming);
        cudaEventCreateWithFlags(&s_ert,  cudaEventDisableTiming);
    }
} s_side_init;

// ---------------- PTX helpers -------------------------------------------------
__device__ __forceinline__ uint32_t smem_u32(const void* p) {
    uint32_t a;
    asm("{ .reg .u64 t; cvta.to.shared.u64 t, %1; cvt.u32.u64 %0, t; }" : "=r"(a) : "l"(p));
    return a;
}
#define CP_ASYNC16(saddr, gptr) \
    asm volatile("cp.async.cg.shared.global [%0], [%1], 16;" :: "r"(saddr), "l"(gptr))
#define CP_ASYNC4(saddr, gptr) \
    asm volatile("cp.async.ca.shared.global [%0], [%1], 4;" :: "r"(saddr), "l"(gptr))
#define CP_COMMIT() asm volatile("cp.async.commit_group;" ::: "memory")
#define CP_WAIT1()  asm volatile("cp.async.wait_group 1;" ::: "memory")
#define CP_WAIT0()  asm volatile("cp.async.wait_group 0;" ::: "memory")

__device__ __forceinline__ uint32_t lds32(uint32_t saddr) {
    uint32_t v;
    asm volatile("ld.shared.b32 %0, [%1];" : "=r"(v) : "r"(saddr));
    return v;
}
// load 2 fp32 from smem, convert to packed fp16x2 (cvt.rn — same as k_convert)
__device__ __forceinline__ uint32_t lds_f32x2_to_h2(uint32_t saddr) {
    float fx, fy;
    asm volatile("ld.shared.v2.f32 {%0,%1}, [%2];" : "=f"(fx), "=f"(fy) : "r"(saddr));
    __half2 h = __floats2half2_rn(fx, fy);
    return *(uint32_t*)&h;
}
__device__ __forceinline__ void mma16816(float* c, const uint32_t* a, const uint32_t* b) {
    asm volatile("mma.sync.aligned.m16n8k16.row.col.f32.f16.f16.f32 "
        "{%0,%1,%2,%3}, {%4,%5,%6,%7}, {%8,%9}, {%0,%1,%2,%3};"
        : "+f"(c[0]), "+f"(c[1]), "+f"(c[2]), "+f"(c[3])
        : "r"(a[0]), "r"(a[1]), "r"(a[2]), "r"(a[3]), "r"(b[0]), "r"(b[1]));
}

// ---------------- prep kernels -------------------------------------------------
__device__ __forceinline__ int head_of(const float* xr) {
    return (xr[0] > 0.5f ? 1 : 0) | (xr[1] > 0.5f ? 2 : 0) | (xr[2] > 0.5f ? 4 : 0);
}
__global__ void k_zeroc() {
    if (threadIdx.x < NHEADS) g_counts[threadIdx.x] = 0;
}
__global__ void k_count(const float* __restrict__ x) {
    __shared__ int hist[NHEADS];
    if (threadIdx.x < NHEADS) hist[threadIdx.x] = 0;
    __syncthreads();
    int b = blockIdx.x * blockDim.x + threadIdx.x;
    if (b < BATCH) atomicAdd(&hist[head_of(x + (size_t)b * XSTRIDE)], 1);
    __syncthreads();
    if (threadIdx.x < NHEADS) atomicAdd(&g_counts[threadIdx.x], hist[threadIdx.x]);
}
__global__ void k_scanzero() {
    if (threadIdx.x == 0) {
        int s = 0, t = 0;
        for (int h = 0; h < NHEADS; h++) {
            int c = g_counts[h];
            g_off[h] = s; g_cursor[h] = s; s += c;
            int nt = (c + 127) / 128;
            for (int m = 0; m < nt && t < MAXTILES; m++)
                g_tilemap[t++] = (h << 16) | m;
        }
        g_ntiles = t;
    }
}
__global__ void k_fillperm(const float* __restrict__ x) {
    int b = blockIdx.x * blockDim.x + threadIdx.x;
    if (b >= BATCH) return;
    int pos = atomicAdd(&g_cursor[head_of(x + (size_t)b * XSTRIDE)], 1);
    g_permsrc[pos] = b;
}
__global__ void k_transpose(const float* __restrict__ in, __half* __restrict__ outp,
                            int R, int C) {
    __shared__ float t[32][33];
    int z = blockIdx.z;
    const float* src = in + (size_t)z * R * C;
    size_t ob = (size_t)z * R * C;
    int c0 = blockIdx.x * 32, r0 = blockIdx.y * 32;
    int tx = threadIdx.x, ty = threadIdx.y;
    #pragma unroll
    for (int i = 0; i < 32; i += 8)
        t[ty + i][tx] = src[(size_t)(r0 + ty + i) * C + c0 + tx];
    __syncthreads();
    #pragma unroll
    for (int i = 0; i < 32; i += 8)
        outp[ob + (size_t)(c0 + ty + i) * R + r0 + tx] = __float2half(t[tx][ty + i]);
}

// ---------------- GEMM1: A = x fp32 via 4B cp.async, B = wbt fp16 --------------
__global__ __launch_bounds__(256, 1)
void gemm1_f32a(const float* __restrict__ x, const __half* __restrict__ B,
                const float* __restrict__ bias, __half* __restrict__ Ch)
{
    extern __shared__ char dsm_raw[];
    char* dsm = (char*)(((uintptr_t)dsm_raw + 1023) & ~(uintptr_t)1023);
    const uint32_t sbase = smem_u32(dsm);
    const int K = DFEAT, N = DBASE;
    const int m0 = blockIdx.y * 128;
    const int n0 = blockIdx.x * BN;
    const int tid = threadIdx.x, wid = tid >> 5, lane = tid & 31;
    const int NC = K / KC1;  // 8

    // A: 128 rows x 64 f32 = 8192 4B cp.async (32/thread, 4B-aligned always)
    // B: 256 rows x 4 16B chunks = 2048 -> wait, 64 f16 = 128B = 8 chunks: 2048
    auto load_stage = [&](int c) {
        const int kt = c * KC1;
        const uint32_t sb = sbase + (c & 1) * STAGE1_B;
        #pragma unroll
        for (int j = 0; j < 32; ++j) {          // A words
            int idx = j * 256 + tid;             // 0..8191
            int r = idx >> 6, w = idx & 63;
            uint32_t dst = sb + OFF1_A + (uint32_t)(r * PITCH_A32 + w * 4);
            CP_ASYNC4(dst, x + (size_t)(m0 + r) * XSTRIDE + NBITS + kt + w);
        }
        #pragma unroll
        for (int j = 0; j < 8; ++j) {           // B 16B chunks
            int idx = j * 256 + tid;             // 0..2047
            int r = idx >> 3, q = idx & 7;
            uint32_t dst = sb + OFF1_B + (uint32_t)(r * PITCH_B16 + q * 16);
            CP_ASYNC16(dst, B + (size_t)(n0 + r) * K + kt + q * 8);
        }
    };
    load_stage(0); CP_COMMIT();

    const int wm = (wid >> 2) * 64, wn = (wid & 3) * 64;
    const int gid = lane >> 2, tig = lane & 3;
    float acc[4][8][4];
    #pragma unroll
    for (int mg = 0; mg < 4; mg++)
        #pragma unroll
        for (int ng = 0; ng < 8; ng++)
            #pragma unroll
            for (int v = 0; v < 4; v++) acc[mg][ng][v] = 0.0f;

    for (int c = 0; c < NC; ++c) {
        if (c + 1 < NC) load_stage(c + 1);
        CP_COMMIT(); CP_WAIT1(); __syncthreads();
        const uint32_t sb = sbase + (c & 1) * STAGE1_B;
        const uint32_t sA = sb + OFF1_A, sB = sb + OFF1_B;
        #pragma unroll
        for (int kk = 0; kk < KC1; kk += 16) {
            uint32_t af[4][4], bfr[8][2];
            const uint32_t ka = (uint32_t)((kk + 2 * tig) * 4);   // fp32: k*4 bytes
            #pragma unroll
            for (int mg = 0; mg < 4; mg++) {
                const uint32_t p0 = (uint32_t)((wm + mg * 16 + gid) * PITCH_A32) + ka;
                af[mg][0] = lds_f32x2_to_h2(sA + p0);
                af[mg][1] = lds_f32x2_to_h2(sA + p0 + 8 * PITCH_A32);
                af[mg][2] = lds_f32x2_to_h2(sA + p0 + 32);
                af[mg][3] = lds_f32x2_to_h2(sA + p0 + 8 * PITCH_A32 + 32);
            }
            const uint32_t kb = (uint32_t)(kk * 2 + tig * 4);
            #pragma unroll
            for (int ng = 0; ng < 8; ng++) {
                const uint32_t p0 = (uint32_t)((wn + ng * 8 + gid) * PITCH_B16) + kb;
                bfr[ng][0] = lds32(sB + p0);
                bfr[ng][1] = lds32(sB + p0 + 16);
            }
            #pragma unroll
            for (int mg = 0; mg < 4; mg++)
                #pragma unroll
                for (int ng = 0; ng < 8; ng++)
                    mma16816(acc[mg][ng], af[mg], bfr[ng]);
        }
        __syncthreads();
    }
    CP_WAIT0();

    const float* bp = bias + n0;
    #pragma unroll
    for (int mg = 0; mg < 4; mg++)
        #pragma unroll
        for (int half = 0; half < 2; half++) {
            const int gm = m0 + wm + mg * 16 + gid + half * 8;
            #pragma unroll
            for (int ng = 0; ng < 8; ng++) {
                const int col = wn + ng * 8 + tig * 2;
                float v0 = fmaxf(acc[mg][ng][half * 2]     + __ldg(bp + col), 0.0f);
                float v1 = fmaxf(acc[mg][ng][half * 2 + 1] + __ldg(bp + col + 1), 0.0f);
                *(__half2*)(Ch + (size_t)gm * N + n0 + col) =
                    __halves2half2(__float2half(v0), __float2half(v1));
            }
        }
}

// ---------------- grouped GEMM (GEMM2 / GEMM3), tile-mapped — R13 core ---------
template<int CMODE, int GATHER>
__global__ __launch_bounds__(256, 1)
void gemm_hmma(const __half* __restrict__ A, const __half* __restrict__ B,
               const float* __restrict__ bias,
               __half* __restrict__ Ch, float* __restrict__ Cf,
               int K, int N)
{
    extern __shared__ char dsm_raw[];
    __shared__ int s_rowidx[128];
    char* dsm = (char*)(((uintptr_t)dsm_raw + 1023) & ~(uintptr_t)1023);
    const uint32_t sbase = smem_u32(dsm);

    if ((int)blockIdx.y >= g_ntiles) return;
    const int e = g_tilemap[blockIdx.y];
    const int head = e >> 16, mtile = e & 0xFFFF;
    const int rowBeg = g_off[head], cnt = g_counts[head];
    const int m0 = rowBeg + mtile * 128;
    const int mValid = min(128, cnt - mtile * 128);
    const int rowEnd = rowBeg + cnt;
    const int n0  = blockIdx.x * BN;
    const int tid = threadIdx.x, wid = tid >> 5, lane = tid & 31;
    const int NC = K / KC;

    if (GATHER) {
        if (tid < 128) {
            int p = m0 + tid;
            s_rowidx[tid] = g_permsrc[p < rowEnd ? p : rowEnd - 1];
        }
        __syncthreads();
    }

    auto load_stage = [&](int c) {
        const int kt = c * KC;
        const uint32_t sb = sbase + (c & 1) * STAGE_B;
        #pragma unroll
        for (int j = 0; j < 24; ++j) {
            int idx = j * 256 + tid;
            const __half* gp; uint32_t dst;
            if (idx < 2048) {
                int r = idx >> 4, q = idx & 15;
                dst = sb + OFF_A + (uint32_t)(r * PITCH + q * 16);
                int rowg = GATHER ? s_rowidx[r] : min(m0 + r, rowEnd - 1);
                gp = A + (size_t)rowg * K + kt + q * 8;
            } else {
                int t2 = idx - 2048;
                int r = t2 >> 4, q = t2 & 15;
                dst = sb + OFF_B + (uint32_t)(r * PITCH + q * 16);
                gp = B + ((size_t)head * N + n0 + r) * K + kt + q * 8;
            }
            CP_ASYNC16(dst, gp);
        }
    };

    load_stage(0); CP_COMMIT();

    const int wm = (wid >> 2) * 64, wn = (wid & 3) * 64;
    const int gid = lane >> 2, tig = lane & 3;
    float acc[4][8][4];
    #pragma unroll
    for (int mg = 0; mg < 4; mg++)
        #pragma unroll
        for (int ng = 0; ng < 8; ng++)
            #pragma unroll
            for (int v = 0; v < 4; v++) acc[mg][ng][v] = 0.0f;

    for (int c = 0; c < NC; ++c) {
        if (c + 1 < NC) load_stage(c + 1);
        CP_COMMIT(); CP_WAIT1(); __syncthreads();
        const uint32_t sb = sbase + (c & 1) * STAGE_B;
        const uint32_t sA = sb + OFF_A, sB = sb + OFF_B;
        #pragma unroll
        for (int kk = 0; kk < KC; kk += 16) {
            const uint32_t kb = (uint32_t)(kk * 2 + tig * 4);
            uint32_t af[4][4], bfr[8][2];
            #pragma unroll
            for (int mg = 0; mg < 4; mg++) {
                const uint32_t p0 = (uint32_t)((wm + mg * 16 + gid) * PITCH) + kb;
                af[mg][0] = lds32(sA + p0);
                af[mg][1] = lds32(sA + p0 + 8 * PITCH);
                af[mg][2] = lds32(sA + p0 + 16);
                af[mg][3] = lds32(sA + p0 + 8 * PITCH + 16);
            }
            #pragma unroll
            for (int ng = 0; ng < 8; ng++) {
                const uint32_t p0 = (uint32_t)((wn + ng * 8 + gid) * PITCH) + kb;
                bfr[ng][0] = lds32(sB + p0);
                bfr[ng][1] = lds32(sB + p0 + 16);
            }
            #pragma unroll
            for (int mg = 0; mg < 4; mg++)
                #pragma unroll
                for (int ng = 0; ng < 8; ng++)
                    mma16816(acc[mg][ng], af[mg], bfr[ng]);
        }
        __syncthreads();
    }
    CP_WAIT0();

    const float* bp = bias + (size_t)head * N + n0;
    #pragma unroll
    for (int mg = 0; mg < 4; mg++)
        #pragma unroll
        for (int half = 0; half < 2; half++) {
            const int mrow = wm + mg * 16 + gid + half * 8;
            if (mrow >= mValid) continue;
            const int gm = m0 + mrow;
            #pragma unroll
            for (int ng = 0; ng < 8; ng++) {
                const int col = wn + ng * 8 + tig * 2;
                float v0 = acc[mg][ng][half * 2]     + __ldg(bp + col);
                float v1 = acc[mg][ng][half * 2 + 1] + __ldg(bp + col + 1);
                if (CMODE == 0) {
                    v0 = fmaxf(v0, 0.0f); v1 = fmaxf(v1, 0.0f);
                    *(__half2*)(Ch + (size_t)gm * N + n0 + col) =
                        __halves2half2(__float2half(v0), __float2half(v1));
                } else {
                    const int orow = g_permsrc[gm];
                    *(float2*)(Cf + (size_t)orow * N + n0 + col) = make_float2(v0, v1);
                }
            }
        }
}

// ---------------- host launcher -------------------------------------------------
extern "C" void kernel_launch(void* const* d_in, const int* in_sizes, int n_in,
                              void* d_out, int out_size)
{
    (void)in_sizes; (void)n_in; (void)out_size;
    const float* x   = (const float*)d_in[0];
    const float* Wb  = (const float*)d_in[1];
    const float* bb  = (const float*)d_in[2];
    const float* Wh1 = (const float*)d_in[3];
    const float* bh1 = (const float*)d_in[4];
    const float* Wh2 = (const float*)d_in[5];
    const float* bh2 = (const float*)d_in[6];
    float* out = (float*)d_out;

    void *p_b, *p_h, *p_wbt, *p_w1t, *p_w2t;
    cudaGetSymbolAddress(&p_b, g_b);
    cudaGetSymbolAddress(&p_h, g_h);
    cudaGetSymbolAddress(&p_wbt, g_wbt);
    cudaGetSymbolAddress(&p_w1t, g_w1t);
    cudaGetSymbolAddress(&p_w2t, g_w2t);

    cudaFuncSetAttribute(gemm1_f32a, cudaFuncAttributeMaxDynamicSharedMemorySize, DSMEM1_BYTES);
    cudaFuncSetAttribute((const void*)gemm_hmma<0,1>, cudaFuncAttributeMaxDynamicSharedMemorySize, DSMEM_BYTES);
    cudaFuncSetAttribute((const void*)gemm_hmma<1,0>, cudaFuncAttributeMaxDynamicSharedMemorySize, DSMEM_BYTES);

    // ---- fork ----
    cudaEventRecord(s_fork, 0);
    cudaStreamWaitEvent(s_side, s_fork, 0);
    cudaStreamWaitEvent(s_rt,   s_fork, 0);

    // side1: weight transposes
    k_transpose<<<dim3(DBASE / 32, DFEAT / 32, 1), dim3(32, 8), 0, s_side>>>(
        Wb, (__half*)p_wbt, DFEAT, DBASE);
    cudaEventRecord(s_ewb, s_side);
    k_transpose<<<dim3(DH / 32, DBASE / 32, NHEADS), dim3(32, 8), 0, s_side>>>(
        Wh1, (__half*)p_w1t, DBASE, DH);
    cudaEventRecord(s_ew1, s_side);
    k_transpose<<<dim3(DOUT / 32, DH / 32, NHEADS), dim3(32, 8), 0, s_side>>>(
        Wh2, (__half*)p_w2t, DH, DOUT);
    cudaEventRecord(s_ew2, s_side);

    // side2: routing (index-only; overlaps GEMM1)
    k_zeroc<<<1, 32, 0, s_rt>>>();
    k_count<<<BATCH / 256, 256, 0, s_rt>>>(x);
    k_scanzero<<<1, 32, 0, s_rt>>>();
    k_fillperm<<<BATCH / 256, 256, 0, s_rt>>>(x);
    cudaEventRecord(s_ert, s_rt);

    // main: GEMM1 (reads x directly) -> GEMM2 -> GEMM3
    cudaStreamWaitEvent(0, s_ewb, 0);
    gemm1_f32a<<<dim3(DBASE / BN, BATCH / 128, 1), 256, DSMEM1_BYTES>>>(
        x, (const __half*)p_wbt, bb, (__half*)p_b);

    cudaStreamWaitEvent(0, s_ert, 0);
    cudaStreamWaitEvent(0, s_ew1, 0);
    gemm_hmma<0,1><<<dim3(DH / BN, MAXTILES, 1), 256, DSMEM_BYTES>>>(
        (const __half*)p_b, (const __half*)p_w1t,
        bh1, (__half*)p_h, nullptr, DBASE, DH);

    cudaStreamWaitEvent(0, s_ew2, 0);
    gemm_hmma<1,0><<<dim3(DOUT / BN, MAXTILES, 1), 256, DSMEM_BYTES>>>(
        (const __half*)p_h, (const __half*)p_w2t,
        bh2, nullptr, out, DH, DOUT);
}